// round 1
// baseline (speedup 1.0000x reference)
#include <cuda_runtime.h>
#include <cstdint>

// Problem constants (x: [32,64,64,64] NCHW fp32, emb*: [512,64] fp32, idx: int)
#define NPIX   131072      // 32 * 64 * 64 pixels
#define D      64          // channel / code dim
#define HW     4096        // 64*64 spatial
#define KMAX   1024
#define CHUNK  64          // codes staged per smem tile (16 KB)
#define TPB    256
#define OUT_ELEMS 8388608  // 32*64*64*64

// Scratch (no cudaMalloc allowed): histogram, half code norms, loss accumulator
__device__ int   g_hist[KMAX];
__device__ float g_halfcn[KMAX];
__device__ float g_lossacc;

__device__ __forceinline__ const float* code_row(int k, const float* e0,
                                                 const float* e1, const float* e2,
                                                 int idxv) {
    if (k < 512) return e0 + (size_t)k * D;
    const float* e = (idxv == 1) ? e1 : e2;
    return e + (size_t)(k - 512) * D;
}

__device__ __forceinline__ uint64_t pack2(float lo, float hi) {
    uint64_t r;
    asm("mov.b64 %0, {%1, %2};" : "=l"(r) : "f"(lo), "f"(hi));
    return r;
}
__device__ __forceinline__ void unpack2(uint64_t v, float& lo, float& hi) {
    asm("mov.b64 {%0, %1}, %2;" : "=f"(lo), "=f"(hi) : "l"(v));
}
// Packed fp32x2 FMA: 2 FMAs per instruction on the fma pipe (Blackwell)
__device__ __forceinline__ void ffma2(uint64_t& acc, uint64_t a, uint64_t b) {
    asm("fma.rn.f32x2 %0, %1, %2, %0;" : "+l"(acc) : "l"(a), "l"(b));
}

// ---------------------------------------------------------------------------
// Kernel 0: zero scratch + precompute 0.5*||c||^2 per code
// ---------------------------------------------------------------------------
__global__ void prep_kernel(const float* __restrict__ e0, const float* __restrict__ e1,
                            const float* __restrict__ e2, const int* __restrict__ idxp) {
    int k = threadIdx.x;             // 1024 threads
    int idxv = *idxp;
    int K = (idxv == 0) ? 512 : 1024;
    g_hist[k] = 0;
    float s = 0.f;
    if (k < K) {
        const float* c = code_row(k, e0, e1, e2, idxv);
        #pragma unroll
        for (int d = 0; d < D; d++) s += c[d] * c[d];
    }
    g_halfcn[k] = 0.5f * s;
    if (k == 0) g_lossacc = 0.f;
}

// ---------------------------------------------------------------------------
// Kernel 1: per-pixel argmin over codes + gather + STE output + loss partials
// One thread = one pixel; x vector (64 fp32) lives in registers as f32x2 pairs.
// ---------------------------------------------------------------------------
__global__ __launch_bounds__(TPB)
void vq_main(const float* __restrict__ X,
             const float* __restrict__ e0, const float* __restrict__ e1,
             const float* __restrict__ e2, const int* __restrict__ idxp,
             float* __restrict__ out) {
    __shared__ float sc[CHUNK][D];   // 16 KB code tile, row-contiguous
    __shared__ float scn[CHUNK];     // half norms for the tile
    __shared__ float red[TPB];

    const int tid = threadIdx.x;
    const int p = blockIdx.x * TPB + tid;       // pixel id = ((b*64+h)*64+w)
    const int idxv = *idxp;
    const int K = (idxv == 0) ? 512 : 1024;
    const int b = p >> 12;
    const int hw = p & (HW - 1);
    const size_t xbase = (size_t)b * (D * HW) + hw;   // NCHW: +c*HW per channel

    // Load this pixel's 64-vector (coalesced across the warp per channel)
    uint64_t xp[D / 2];
    #pragma unroll
    for (int j = 0; j < D / 2; j++) {
        float lo = X[xbase + (size_t)(2 * j) * HW];
        float hi = X[xbase + (size_t)(2 * j + 1) * HW];
        xp[j] = pack2(lo, hi);
    }

    // argmax of score = x.c - 0.5||c||^2  (== argmin distance), track top-2
    float s1 = -3.4e38f, s2 = -3.4e38f;
    int i1 = 0, i2 = 0;

    for (int kc = 0; kc < K; kc += CHUNK) {
        // Stage CHUNK codes into shared (coalesced global reads)
        for (int i = tid; i < CHUNK * D; i += TPB) {
            int r = i >> 6, d = i & 63;
            sc[r][d] = code_row(kc + r, e0, e1, e2, idxv)[d];
        }
        if (tid < CHUNK) scn[tid] = g_halfcn[kc + tid];
        __syncthreads();

        #pragma unroll 4
        for (int k = 0; k < CHUNK; k++) {
            const ulonglong2* cp = (const ulonglong2*)sc[k];  // broadcast LDS.128
            uint64_t a0 = 0, a1 = 0, a2 = 0, a3 = 0;          // (0.f,0.f) packs
            #pragma unroll
            for (int j = 0; j < 8; j++) {
                ulonglong2 cc = cp[2 * j];
                ulonglong2 cd = cp[2 * j + 1];
                ffma2(a0, xp[4 * j + 0], cc.x);
                ffma2(a1, xp[4 * j + 1], cc.y);
                ffma2(a2, xp[4 * j + 2], cd.x);
                ffma2(a3, xp[4 * j + 3], cd.y);
            }
            float l0, h0, l1, h1, l2, h2, l3, h3;
            unpack2(a0, l0, h0); unpack2(a1, l1, h1);
            unpack2(a2, l2, h2); unpack2(a3, l3, h3);
            float dot = ((l0 + h0) + (l1 + h1)) + ((l2 + h2) + (l3 + h3));
            float s = dot - scn[k];
            int kk = kc + k;
            if (s > s1)      { s2 = s1; i2 = i1; s1 = s; i1 = kk; }
            else if (s > s2) { s2 = s;  i2 = kk; }
        }
        __syncthreads();
    }

    // Rescue near-ties in fp64 (distance margin < 1e-3; ~1e-4 of pixels)
    if (s1 - s2 < 5e-4f) {
        const float* c1 = code_row(i1, e0, e1, e2, idxv);
        const float* c2 = code_row(i2, e0, e1, e2, idxv);
        double d1 = 0.0, d2 = 0.0;
        for (int j = 0; j < D / 2; j++) {
            float lo, hi; unpack2(xp[j], lo, hi);
            double t;
            t = (double)lo - (double)c1[2 * j];     d1 += t * t;
            t = (double)hi - (double)c1[2 * j + 1]; d1 += t * t;
            t = (double)lo - (double)c2[2 * j];     d2 += t * t;
            t = (double)hi - (double)c2[2 * j + 1]; d2 += t * t;
        }
        if (d2 < d1 || (d2 == d1 && i2 < i1)) i1 = i2;
    }

    atomicAdd(&g_hist[i1], 1);

    // Gather winning code, write STE output (x + (q - x), matching reference
    // rounding), accumulate squared error
    const float* cw = code_row(i1, e0, e1, e2, idxv);
    float lsum = 0.f;
    #pragma unroll
    for (int j = 0; j < D / 2; j++) {
        float lo, hi; unpack2(xp[j], lo, hi);
        float q0 = cw[2 * j], q1 = cw[2 * j + 1];
        float dl = q0 - lo, dh = q1 - hi;
        out[xbase + (size_t)(2 * j) * HW]     = lo + dl;
        out[xbase + (size_t)(2 * j + 1) * HW] = hi + dh;
        lsum += dl * dl + dh * dh;
    }

    // Block-reduce loss partials, one atomic per block
    red[tid] = lsum;
    __syncthreads();
    for (int off = TPB / 2; off > 0; off >>= 1) {
        if (tid < off) red[tid] += red[tid + off];
        __syncthreads();
    }
    if (tid == 0) atomicAdd(&g_lossacc, red[0]);
}

// ---------------------------------------------------------------------------
// Kernel 2: finalize loss + perplexity, write scalars
// ---------------------------------------------------------------------------
__global__ void finalize_kernel(const int* __restrict__ idxp, float* __restrict__ out,
                                int out_size) {
    __shared__ float red[1024];
    int t = threadIdx.x;
    int idxv = *idxp;
    int K = (idxv == 0) ? 512 : 1024;
    float v = 0.f;
    if (t < K) {
        float pr = (float)g_hist[t] * (1.0f / (float)NPIX);  // /2^17 exact
        v = pr * logf(pr + 1e-10f);
    }
    red[t] = v;
    __syncthreads();
    for (int off = 512; off > 0; off >>= 1) {
        if (t < off) red[t] += red[t + off];
        __syncthreads();
    }
    if (t == 0) {
        float mse = g_lossacc / (float)OUT_ELEMS;
        out[OUT_ELEMS]     = mse + 0.25f * mse;   // q_latent + 0.25*e_latent
        out[OUT_ELEMS + 1] = expf(-red[0]);       // perplexity
    }
    // Defensive: zero any tail beyond the known outputs (d_out is poisoned)
    for (int i = OUT_ELEMS + 2 + t; i < out_size; i += 1024) out[i] = 0.f;
}

// ---------------------------------------------------------------------------
extern "C" void kernel_launch(void* const* d_in, const int* in_sizes, int n_in,
                              void* d_out, int out_size) {
    const float* x  = (const float*)d_in[0];
    const float* e0 = (const float*)d_in[1];
    const float* e1 = (const float*)d_in[2];
    const float* e2 = (const float*)d_in[3];
    const int*   ip = (const int*)d_in[4];
    float* out = (float*)d_out;

    prep_kernel<<<1, 1024>>>(e0, e1, e2, ip);
    vq_main<<<NPIX / TPB, TPB>>>(x, e0, e1, e2, ip, out);
    finalize_kernel<<<1, 1024>>>(ip, out, out_size);
}

// round 2
// speedup vs baseline: 1.0288x; 1.0288x over previous
#include <cuda_runtime.h>
#include <cstdint>

// Problem constants (x: [32,64,64,64] NCHW fp32, emb*: [512,64] fp32, idx: int)
#define NPIX   131072      // 32 * 64 * 64 pixels
#define D      64          // channel / code dim
#define HW     4096        // 64*64 spatial
#define KMAX   1024
#define CHUNK  32          // codes per smem tile (duplicated: 16 KB)
#define TPB    128
#define PPB    256         // pixels per block (2 per thread)
#define OUT_ELEMS 8388608  // 32*64*64*64

// Scratch (no cudaMalloc allowed)
__device__ int   g_hist[KMAX];
__device__ float g_halfcn[KMAX];
__device__ float g_lossacc;

__device__ __forceinline__ const float* code_row(int k, const float* e0,
                                                 const float* e1, const float* e2,
                                                 int idxv) {
    if (k < 512) return e0 + (size_t)k * D;
    const float* e = (idxv == 1) ? e1 : e2;
    return e + (size_t)(k - 512) * D;
}

__device__ __forceinline__ uint64_t pack2(float lo, float hi) {
    uint64_t r;
    asm("mov.b64 %0, {%1, %2};" : "=l"(r) : "f"(lo), "f"(hi));
    return r;
}
__device__ __forceinline__ void unpack2(uint64_t v, float& lo, float& hi) {
    asm("mov.b64 {%0, %1}, %2;" : "=f"(lo), "=f"(hi) : "l"(v));
}
// Packed fp32x2 FMA / ADD: 2 ops per instruction on the fma pipe
__device__ __forceinline__ void ffma2(uint64_t& acc, uint64_t a, uint64_t b) {
    asm("fma.rn.f32x2 %0, %1, %2, %0;" : "+l"(acc) : "l"(a), "l"(b));
}
__device__ __forceinline__ uint64_t fadd2(uint64_t a, uint64_t b) {
    uint64_t r;
    asm("add.rn.f32x2 %0, %1, %2;" : "=l"(r) : "l"(a), "l"(b));
    return r;
}

// ---------------------------------------------------------------------------
// Kernel 0: zero scratch + precompute 0.5*||c||^2 (one warp per code)
// 128 blocks x 128 threads = 1024 warps
// ---------------------------------------------------------------------------
__global__ void prep_kernel(const float* __restrict__ e0, const float* __restrict__ e1,
                            const float* __restrict__ e2, const int* __restrict__ idxp) {
    int idxv = *idxp;
    int K = (idxv == 0) ? 512 : 1024;
    int lane = threadIdx.x & 31;
    int k = blockIdx.x * 4 + (threadIdx.x >> 5);   // global warp id = code id
    float s = 0.f;
    if (k < K) {
        const float* c = code_row(k, e0, e1, e2, idxv);
        float a = c[lane], b = c[lane + 32];
        s = a * a + b * b;
    }
    #pragma unroll
    for (int off = 16; off > 0; off >>= 1)
        s += __shfl_xor_sync(0xffffffffu, s, off);
    if (lane == 0) {
        g_halfcn[k] = 0.5f * s;
        g_hist[k] = 0;
        if (k == 0) g_lossacc = 0.f;
    }
}

// ---------------------------------------------------------------------------
// Kernel 1: per-pixel argmin + gather + STE output + loss partials.
// Two pixels per thread, packed into the two halves of f32x2 lanes.
// Codes staged into shared PRE-DUPLICATED: scdup[k][d] = (c_d, c_d).
// score = x.c - 0.5||c||^2 (argmax == argmin distance); -0.5||c||^2 folded
// into the accumulator init so there is no epilogue subtract, and the
// horizontal reduction is 3 packed adds (no scalar unpack/adds per code).
// ---------------------------------------------------------------------------
__global__ __launch_bounds__(TPB)
void vq_main(const float* __restrict__ X,
             const float* __restrict__ e0, const float* __restrict__ e1,
             const float* __restrict__ e2, const int* __restrict__ idxp,
             float* __restrict__ out) {
    __shared__ __align__(16) uint64_t scdup[CHUNK * D];  // 16 KB duplicated codes
    __shared__ uint64_t scn2[CHUNK];                     // (-0.5||c||^2) duplicated
    __shared__ float red[TPB];

    const int tid = threadIdx.x;
    const int idxv = *idxp;
    const int K = (idxv == 0) ? 512 : 1024;
    const int pA = blockIdx.x * PPB + tid;      // pixel for lo half
    const int pB = pA + TPB;                    // pixel for hi half (same batch b)
    const int b = pA >> 12;
    const size_t xbA = (size_t)b * (D * HW) + (pA & (HW - 1));
    const size_t xbB = (size_t)b * (D * HW) + (pB & (HW - 1));

    // Load both pixels' 64-vectors, packed (xA_d, xB_d)
    uint64_t xp[D];
    #pragma unroll
    for (int d = 0; d < D; d++)
        xp[d] = pack2(X[xbA + (size_t)d * HW], X[xbB + (size_t)d * HW]);

    float s1A = -3.4e38f, s2A = -3.4e38f, s1B = -3.4e38f, s2B = -3.4e38f;
    int i1A = 0, i2A = 0, i1B = 0, i2B = 0;

    for (int kc = 0; kc < K; kc += CHUNK) {
        // Stage CHUNK codes, duplicated. A chunk never straddles the 512 boundary.
        const float* src = (kc < 512)
            ? e0 + (size_t)kc * D
            : ((idxv == 1) ? e1 : e2) + (size_t)(kc - 512) * D;
        #pragma unroll
        for (int i = tid; i < CHUNK * D; i += TPB) {
            float v = src[i];
            scdup[i] = pack2(v, v);
        }
        if (tid < CHUNK) {
            float h = g_halfcn[kc + tid];
            scn2[tid] = pack2(-h, -h);
        }
        __syncthreads();

        #pragma unroll 2
        for (int k = 0; k < CHUNK; k++) {
            const ulonglong2* cp = (const ulonglong2*)(scdup + k * D);
            uint64_t a0 = scn2[k], a1 = 0ull, a2 = 0ull, a3 = 0ull;
            #pragma unroll
            for (int j = 0; j < 8; j++) {
                ulonglong2 c0 = cp[4 * j + 0];
                ulonglong2 c1 = cp[4 * j + 1];
                ulonglong2 c2 = cp[4 * j + 2];
                ulonglong2 c3 = cp[4 * j + 3];
                ffma2(a0, xp[8 * j + 0], c0.x);
                ffma2(a1, xp[8 * j + 1], c0.y);
                ffma2(a2, xp[8 * j + 2], c1.x);
                ffma2(a3, xp[8 * j + 3], c1.y);
                ffma2(a0, xp[8 * j + 4], c2.x);
                ffma2(a1, xp[8 * j + 5], c2.y);
                ffma2(a2, xp[8 * j + 6], c3.x);
                ffma2(a3, xp[8 * j + 7], c3.y);
            }
            uint64_t s01 = fadd2(a0, a1);
            uint64_t s23 = fadd2(a2, a3);
            uint64_t ss  = fadd2(s01, s23);
            float sA, sB;
            unpack2(ss, sA, sB);
            int kk = kc + k;
            if (sA > s1A)      { s2A = s1A; i2A = i1A; s1A = sA; i1A = kk; }
            else if (sA > s2A) { s2A = sA;  i2A = kk; }
            if (sB > s1B)      { s2B = s1B; i2B = i1B; s1B = sB; i1B = kk; }
            else if (sB > s2B) { s2B = sB;  i2B = kk; }
        }
        __syncthreads();
    }

    // fp64 rescue for near-ties (distance margin < ~1e-3); ~1e-4 of pixels
    {
        if (s1A - s2A < 5e-4f) {
            const float* c1 = code_row(i1A, e0, e1, e2, idxv);
            const float* c2 = code_row(i2A, e0, e1, e2, idxv);
            double d1 = 0.0, d2 = 0.0;
            for (int d = 0; d < D; d++) {
                float lo, hi; unpack2(xp[d], lo, hi); (void)hi;
                double t1 = (double)lo - (double)c1[d]; d1 += t1 * t1;
                double t2 = (double)lo - (double)c2[d]; d2 += t2 * t2;
            }
            if (d2 < d1 || (d2 == d1 && i2A < i1A)) i1A = i2A;
        }
        if (s1B - s2B < 5e-4f) {
            const float* c1 = code_row(i1B, e0, e1, e2, idxv);
            const float* c2 = code_row(i2B, e0, e1, e2, idxv);
            double d1 = 0.0, d2 = 0.0;
            for (int d = 0; d < D; d++) {
                float lo, hi; unpack2(xp[d], lo, hi); (void)lo;
                double t1 = (double)hi - (double)c1[d]; d1 += t1 * t1;
                double t2 = (double)hi - (double)c2[d]; d2 += t2 * t2;
            }
            if (d2 < d1 || (d2 == d1 && i2B < i1B)) i1B = i2B;
        }
    }

    atomicAdd(&g_hist[i1A], 1);
    atomicAdd(&g_hist[i1B], 1);

    // Gather winners, STE output (x + (q - x), reference rounding), loss partial
    const float* cA = code_row(i1A, e0, e1, e2, idxv);
    const float* cB = code_row(i1B, e0, e1, e2, idxv);
    float lsum = 0.f;
    #pragma unroll
    for (int d = 0; d < D; d++) {
        float lo, hi; unpack2(xp[d], lo, hi);
        float dA = cA[d] - lo, dB = cB[d] - hi;
        out[xbA + (size_t)d * HW] = lo + dA;
        out[xbB + (size_t)d * HW] = hi + dB;
        lsum += dA * dA + dB * dB;
    }

    red[tid] = lsum;
    __syncthreads();
    for (int off = TPB / 2; off > 0; off >>= 1) {
        if (tid < off) red[tid] += red[tid + off];
        __syncthreads();
    }
    if (tid == 0) atomicAdd(&g_lossacc, red[0]);
}

// ---------------------------------------------------------------------------
// Kernel 2: finalize loss + perplexity
// ---------------------------------------------------------------------------
__global__ void finalize_kernel(const int* __restrict__ idxp, float* __restrict__ out,
                                int out_size) {
    __shared__ float red[1024];
    int t = threadIdx.x;
    int idxv = *idxp;
    int K = (idxv == 0) ? 512 : 1024;
    float v = 0.f;
    if (t < K) {
        float pr = (float)g_hist[t] * (1.0f / (float)NPIX);
        v = pr * logf(pr + 1e-10f);
    }
    red[t] = v;
    __syncthreads();
    for (int off = 512; off > 0; off >>= 1) {
        if (t < off) red[t] += red[t + off];
        __syncthreads();
    }
    if (t == 0) {
        float mse = g_lossacc / (float)OUT_ELEMS;
        out[OUT_ELEMS]     = mse + 0.25f * mse;   // q_latent + 0.25*e_latent
        out[OUT_ELEMS + 1] = expf(-red[0]);       // perplexity
    }
    for (int i = OUT_ELEMS + 2 + t; i < out_size; i += 1024) out[i] = 0.f;
}

// ---------------------------------------------------------------------------
extern "C" void kernel_launch(void* const* d_in, const int* in_sizes, int n_in,
                              void* d_out, int out_size) {
    const float* x  = (const float*)d_in[0];
    const float* e0 = (const float*)d_in[1];
    const float* e1 = (const float*)d_in[2];
    const float* e2 = (const float*)d_in[3];
    const int*   ip = (const int*)d_in[4];
    float* out = (float*)d_out;

    prep_kernel<<<256, 128>>>(e0, e1, e2, ip);
    vq_main<<<NPIX / PPB, TPB>>>(x, e0, e1, e2, ip, out);
    finalize_kernel<<<1, 1024>>>(ip, out, out_size);
}

// round 5
// speedup vs baseline: 2.6134x; 2.5402x over previous
#include <cuda_runtime.h>
#include <cuda_bf16.h>
#include <cstdint>

// Problem: x [32,64,64,64] NCHW fp32, emb0/1/2 [512,64] fp32, idx int
#define NPIX   131072
#define D      64
#define HW     4096
#define KMAX   1024
#define OUT_ELEMS 8388608
#define CTA_PIX 256
#define TPB    256

// smem layout (bytes)
#define SM_A    0            // 256 rows x 256B   (xh|xl bf16, swizzled)
#define SM_B    65536        // 256 rows x 256B   (ch|cl bf16, swizzled)
#define SM_SHN2 131072       // 1024 u32 packed (-norm hi, -norm lo) bf16
#define SM_S1   135168       // 256 f32
#define SM_S2   136192
#define SM_I1   137216       // 256 i32
#define SM_I2   138240
#define SM_RED  139264       // 256 f32
#define SMEM_TOTAL 140288

// Scratch (no cudaMalloc allowed)
__device__ int      g_hist[KMAX];
__device__ uint32_t g_shn2[KMAX];
__device__ float    g_lossacc;
// Pre-split codes, swizzled chunk layout: 4 chunks x 256 rows x 256B
__device__ __align__(16) unsigned char g_bsplit[KMAX * 256];

// ---------------------------------------------------------------------------
__device__ __forceinline__ uint32_t smem_u32(const void* p) {
    uint32_t a;
    asm("{ .reg .u64 t; cvta.to.shared.u64 t, %1; cvt.u32.u64 %0, t; }"
        : "=r"(a) : "l"(p));
    return a;
}

#define LDSM_X4(r0, r1, r2, r3, addr) \
    asm volatile("ldmatrix.sync.aligned.m8n8.x4.shared.b16 {%0,%1,%2,%3}, [%4];" \
        : "=r"(r0), "=r"(r1), "=r"(r2), "=r"(r3) : "r"(addr))

#define MMA(dd, a0, a1, a2, a3, b0, b1) \
    asm volatile("mma.sync.aligned.m16n8k16.row.col.f32.bf16.bf16.f32 " \
        "{%0,%1,%2,%3},{%4,%5,%6,%7},{%8,%9},{%0,%1,%2,%3};" \
        : "+f"((dd)[0]), "+f"((dd)[1]), "+f"((dd)[2]), "+f"((dd)[3]) \
        : "r"(a0), "r"(a1), "r"(a2), "r"(a3), "r"(b0), "r"(b1))

__device__ __forceinline__ const float* code_row(int k, const float* e0,
                                                 const float* e1, const float* e2,
                                                 int idxv) {
    if (k < 512) return e0 + (size_t)k * D;
    const float* e = (idxv == 1) ? e1 : e2;
    return e + (size_t)(k - 512) * D;
}

// ---------------------------------------------------------------------------
// Kernel 0: zero hist/loss + packed bf16-split of (-0.5*||c||^2) per code
// ---------------------------------------------------------------------------
__global__ void prep_norms(const float* __restrict__ e0, const float* __restrict__ e1,
                           const float* __restrict__ e2, const int* __restrict__ idxp) {
    int idxv = *idxp;
    int K = (idxv == 0) ? 512 : 1024;
    int lane = threadIdx.x & 31;
    int k = blockIdx.x * 4 + (threadIdx.x >> 5);
    float s = 0.f;
    if (k < K) {
        const float* c = code_row(k, e0, e1, e2, idxv);
        float a = c[lane], b = c[lane + 32];
        s = a * a + b * b;
    }
    #pragma unroll
    for (int off = 16; off > 0; off >>= 1) s += __shfl_xor_sync(0xffffffffu, s, off);
    if (lane == 0) {
        float neg = -0.5f * s;
        __nv_bfloat16 nh = __float2bfloat16_rn(neg);
        __nv_bfloat16 nl = __float2bfloat16_rn(neg - __bfloat162float(nh));
        g_shn2[k] = (uint32_t)__bfloat16_as_ushort(nh)
                  | ((uint32_t)__bfloat16_as_ushort(nl) << 16);
        g_hist[k] = 0;
        if (k == 0) g_lossacc = 0.f;
    }
}

// ---------------------------------------------------------------------------
// Kernel 1: bf16-split codes -> g_bsplit, swizzled for ldmatrix.
// row = code%256 within chunk; ch at byte cols 0..127, cl at 128..255.
// swizzle: 16B-unit u -> u ^ (row&7)
// ---------------------------------------------------------------------------
__global__ void prep_bsplit(const float* __restrict__ e0, const float* __restrict__ e1,
                            const float* __restrict__ e2, const int* __restrict__ idxp) {
    int idxv = *idxp;
    int K = (idxv == 0) ? 512 : 1024;
    int k = blockIdx.x;
    if (k >= K) return;
    int d = threadIdx.x;                       // 0..63
    float v = code_row(k, e0, e1, e2, idxv)[d];
    __nv_bfloat16 hb = __float2bfloat16_rn(v);
    __nv_bfloat16 lb = __float2bfloat16_rn(v - __bfloat162float(hb));
    unsigned char* buf = g_bsplit + (size_t)(k >> 8) * 65536;
    int r = k & 255;
    int u = d >> 3;                            // (2d)/16
    int inb = (2 * d) & 15;
    *(__nv_bfloat16*)(buf + r * 256 + (((u)     ^ (r & 7)) << 4) + inb) = hb;
    *(__nv_bfloat16*)(buf + r * 256 + (((u + 8) ^ (r & 7)) << 4) + inb) = lb;
}

// ---------------------------------------------------------------------------
// Kernel 2: HMMA scoring + top-2 argmax + rescue + output/loss/hist.
// score = x.c - 0.5||c||^2 via bf16 split (xh.ch + xh.cl + xl.ch) plus a
// norm k-tile (A col of ones x B col of split -norm). argmax == argmin dist.
// ---------------------------------------------------------------------------
__global__ __launch_bounds__(TPB, 1)
void vq_hmma(const float* __restrict__ X,
             const float* __restrict__ e0, const float* __restrict__ e1,
             const float* __restrict__ e2, const int* __restrict__ idxp,
             float* __restrict__ out) {
    extern __shared__ __align__(1024) char smem[];
    const uint32_t sb = smem_u32(smem);
    const int tid = threadIdx.x;
    const int warp = tid >> 5, lane = tid & 31;
    const int q = lane & 3, lr = lane & 7, grp = lane >> 3;
    const int idxv = *idxp;
    const int K = (idxv == 0) ? 512 : 1024;
    const int nch = K >> 8;
    const int pbase = blockIdx.x * CTA_PIX;

    // ---- stage A tile (xh|xl) swizzled + shn2 into smem ----
    {
        int r = tid;
        int p = pbase + r;
        int b = p >> 12;
        size_t xb = (size_t)b * (D * HW) + (p & (HW - 1));
        #pragma unroll
        for (int j = 0; j < 32; j++) {
            float v0 = X[xb + (size_t)(2 * j) * HW];
            float v1 = X[xb + (size_t)(2 * j + 1) * HW];
            __nv_bfloat16 h0 = __float2bfloat16_rn(v0), h1 = __float2bfloat16_rn(v1);
            __nv_bfloat16 l0 = __float2bfloat16_rn(v0 - __bfloat162float(h0));
            __nv_bfloat16 l1 = __float2bfloat16_rn(v1 - __bfloat162float(h1));
            uint32_t hp = (uint32_t)__bfloat16_as_ushort(h0)
                        | ((uint32_t)__bfloat16_as_ushort(h1) << 16);
            uint32_t lp = (uint32_t)__bfloat16_as_ushort(l0)
                        | ((uint32_t)__bfloat16_as_ushort(l1) << 16);
            int u = j >> 2;                 // byte col 4j -> 16B unit
            int inb = (4 * j) & 15;
            *(uint32_t*)(smem + SM_A + r * 256 + (((u)     ^ (r & 7)) << 4) + inb) = hp;
            *(uint32_t*)(smem + SM_A + r * 256 + (((u + 8) ^ (r & 7)) << 4) + inb) = lp;
        }
        uint32_t* sh2 = (uint32_t*)(smem + SM_SHN2);
        for (int i = tid; i < KMAX; i += TPB) sh2[i] = g_shn2[i];
    }
    __syncthreads();

    // ---- load persistent A fragments: xh/xl [mtile][ktile][4 regs] ----
    uint32_t xh[2][4][4], xl[2][4][4];
    #pragma unroll
    for (int mt = 0; mt < 2; mt++)
        #pragma unroll
        for (int kt = 0; kt < 4; kt++) {
            int row = warp * 32 + mt * 16 + ((grp & 1) << 3) + lr;
            int uh = kt * 2 + (grp >> 1);
            LDSM_X4(xh[mt][kt][0], xh[mt][kt][1], xh[mt][kt][2], xh[mt][kt][3],
                    sb + SM_A + row * 256 + (((uh) ^ lr) << 4));
            int ul = 8 + kt * 2 + (grp >> 1);
            LDSM_X4(xl[mt][kt][0], xl[mt][kt][1], xl[mt][kt][2], xl[mt][kt][3],
                    sb + SM_A + row * 256 + (((ul) ^ lr) << 4));
        }

    // top-2 per pixel-slot: slot = mt*2 + rowhalf (rows lane/4 and lane/4+8)
    float s1[4], s2[4];
    int i1[4], i2[4];
    #pragma unroll
    for (int sl = 0; sl < 4; sl++) { s1[sl] = -3.4e38f; s2[sl] = -3.4e38f; i1[sl] = 0; i2[sl] = 0; }

    const uint32_t aext = (q == 0) ? 0x3F803F80u : 0u;   // (1.0,1.0) bf16
    const uint32_t* sh2 = (const uint32_t*)(smem + SM_SHN2);

    for (int ch = 0; ch < nch; ch++) {
        // stage B chunk (64 KB, swizzle preserved by raw copy)
        {
            const uint4* src = (const uint4*)(g_bsplit + (size_t)ch * 65536);
            uint4* dst = (uint4*)(smem + SM_B);
            #pragma unroll
            for (int i = 0; i < 16; i++) dst[tid + i * TPB] = src[tid + i * TPB];
        }
        __syncthreads();
        const int kb = ch << 8;

        #pragma unroll 1
        for (int ng = 0; ng < 16; ng++) {
            const int nt0 = ng * 2;
            float dx[2][2][4];                       // [mtile][ntile][reg]
            #pragma unroll
            for (int a = 0; a < 2; a++)
                #pragma unroll
                for (int bb = 0; bb < 2; bb++)
                    #pragma unroll
                    for (int c = 0; c < 4; c++) dx[a][bb][c] = 0.f;

            // norm k-tile: ones-column (k0,k1) x (-norm hi, -norm lo).
            // A fragment: a0 = rows lane/4 @ k0-1, a1 = rows lane/4+8 @ k0-1
            // (a1 MUST carry the ones too — rows 8-15 of each m-tile).
            uint32_t be0 = 0, be1 = 0;
            if (q == 0) {
                be0 = sh2[kb + nt0 * 8 + (lane >> 2)];
                be1 = sh2[kb + nt0 * 8 + 8 + (lane >> 2)];
            }
            MMA(dx[0][0], aext, aext, 0u, 0u, be0, 0u);
            MMA(dx[0][1], aext, aext, 0u, 0u, be1, 0u);
            MMA(dx[1][0], aext, aext, 0u, 0u, be0, 0u);
            MMA(dx[1][1], aext, aext, 0u, 0u, be1, 0u);

            #pragma unroll
            for (int s = 0; s < 3; s++) {            // xh.ch, xh.cl, xl.ch
                const int bsplit = (s == 1) ? 8 : 0;
                #pragma unroll
                for (int p2 = 0; p2 < 2; p2++) {     // ktile pairs
                    uint32_t b0[4], b1[4];
                    {
                        int u = bsplit + p2 * 4 + grp;
                        int row0 = nt0 * 8 + lr;
                        LDSM_X4(b0[0], b0[1], b0[2], b0[3],
                                sb + SM_B + row0 * 256 + (((u) ^ lr) << 4));
                        int row1 = (nt0 + 1) * 8 + lr;
                        LDSM_X4(b1[0], b1[1], b1[2], b1[3],
                                sb + SM_B + row1 * 256 + (((u) ^ lr) << 4));
                    }
                    #pragma unroll
                    for (int k2 = 0; k2 < 2; k2++) {
                        const int kt = p2 * 2 + k2;
                        if (s == 2) {
                            MMA(dx[0][0], xl[0][kt][0], xl[0][kt][1], xl[0][kt][2], xl[0][kt][3], b0[k2*2], b0[k2*2+1]);
                            MMA(dx[0][1], xl[0][kt][0], xl[0][kt][1], xl[0][kt][2], xl[0][kt][3], b1[k2*2], b1[k2*2+1]);
                            MMA(dx[1][0], xl[1][kt][0], xl[1][kt][1], xl[1][kt][2], xl[1][kt][3], b0[k2*2], b0[k2*2+1]);
                            MMA(dx[1][1], xl[1][kt][0], xl[1][kt][1], xl[1][kt][2], xl[1][kt][3], b1[k2*2], b1[k2*2+1]);
                        } else {
                            MMA(dx[0][0], xh[0][kt][0], xh[0][kt][1], xh[0][kt][2], xh[0][kt][3], b0[k2*2], b0[k2*2+1]);
                            MMA(dx[0][1], xh[0][kt][0], xh[0][kt][1], xh[0][kt][2], xh[0][kt][3], b1[k2*2], b1[k2*2+1]);
                            MMA(dx[1][0], xh[1][kt][0], xh[1][kt][1], xh[1][kt][2], xh[1][kt][3], b0[k2*2], b0[k2*2+1]);
                            MMA(dx[1][1], xh[1][kt][0], xh[1][kt][1], xh[1][kt][2], xh[1][kt][3], b1[k2*2], b1[k2*2+1]);
                        }
                    }
                }
            }

            // epilogue: top-2 update. D frag: d0,d1 = (row lane/4, cols n,n+1);
            // d2,d3 = (row lane/4+8, cols n,n+1); n = kb + ntile*8 + 2q
            #pragma unroll
            for (int mt = 0; mt < 2; mt++)
                #pragma unroll
                for (int j = 0; j < 2; j++) {
                    const int nb = kb + (nt0 + j) * 8 + q * 2;
                    #pragma unroll
                    for (int e = 0; e < 4; e++) {
                        const int sl = mt * 2 + (e >> 1);
                        const int kk = nb + (e & 1);
                        float v = dx[mt][j][e];
                        if (v > s2[sl]) {
                            if (v > s1[sl]) { s2[sl] = s1[sl]; i2[sl] = i1[sl]; s1[sl] = v; i1[sl] = kk; }
                            else            { s2[sl] = v; i2[sl] = kk; }
                        }
                    }
                }
        }
        __syncthreads();
    }

    // ---- merge top-2 across the quad (lanes sharing a row) ----
    #pragma unroll
    for (int sl = 0; sl < 4; sl++) {
        #pragma unroll
        for (int m = 1; m <= 2; m <<= 1) {
            float o1 = __shfl_xor_sync(0xffffffffu, s1[sl], m);
            float o2 = __shfl_xor_sync(0xffffffffu, s2[sl], m);
            int oi1 = __shfl_xor_sync(0xffffffffu, i1[sl], m);
            int oi2 = __shfl_xor_sync(0xffffffffu, i2[sl], m);
            if (o1 > s1[sl]) {
                float ns2; int ni2;
                if (o2 > s1[sl]) { ns2 = o2; ni2 = oi2; }
                else             { ns2 = s1[sl]; ni2 = i1[sl]; }
                s1[sl] = o1; i1[sl] = oi1; s2[sl] = ns2; i2[sl] = ni2;
            } else if (o1 > s2[sl]) { s2[sl] = o1; i2[sl] = oi1; }
        }
    }
    if (q == 0) {
        #pragma unroll
        for (int sl = 0; sl < 4; sl++) {
            int mt = sl >> 1, rs = sl & 1;
            int pl = warp * 32 + mt * 16 + rs * 8 + (lane >> 2);
            ((float*)(smem + SM_S1))[pl] = s1[sl];
            ((float*)(smem + SM_S2))[pl] = s2[sl];
            ((int*)(smem + SM_I1))[pl] = i1[sl];
            ((int*)(smem + SM_I2))[pl] = i2[sl];
        }
    }
    __syncthreads();

    // ---- phase 2: rescue near-ties, then gather/output/loss/hist ----
    {
        int p = pbase + tid;
        int b = p >> 12;
        size_t xb = (size_t)b * (D * HW) + (p & (HW - 1));
        float fs1 = ((float*)(smem + SM_S1))[tid];
        float fs2 = ((float*)(smem + SM_S2))[tid];
        int w1 = ((int*)(smem + SM_I1))[tid];
        int w2 = ((int*)(smem + SM_I2))[tid];

        if (fs1 - fs2 < 4e-3f) {                 // covers split + norm error
            const float* c1 = code_row(w1, e0, e1, e2, idxv);
            const float* c2 = code_row(w2, e0, e1, e2, idxv);
            double d1 = 0.0, d2 = 0.0;
            for (int d = 0; d < D; d++) {
                double xv = (double)X[xb + (size_t)d * HW];
                double t1 = xv - (double)c1[d]; d1 += t1 * t1;
                double t2 = xv - (double)c2[d]; d2 += t2 * t2;
            }
            if (d2 < d1 || (d2 == d1 && w2 < w1)) w1 = w2;
        }
        atomicAdd(&g_hist[w1], 1);

        const float* cw = code_row(w1, e0, e1, e2, idxv);
        float lsum = 0.f;
        #pragma unroll 8
        for (int d = 0; d < D; d++) {
            float xv = X[xb + (size_t)d * HW];
            float df = cw[d] - xv;
            out[xb + (size_t)d * HW] = xv + df;   // STE, reference rounding
            lsum += df * df;
        }
        float* red = (float*)(smem + SM_RED);
        red[tid] = lsum;
        __syncthreads();
        for (int off = TPB / 2; off > 0; off >>= 1) {
            if (tid < off) red[tid] += red[tid + off];
            __syncthreads();
        }
        if (tid == 0) atomicAdd(&g_lossacc, red[0]);
    }
}

// ---------------------------------------------------------------------------
// Kernel 3: finalize loss + perplexity
// ---------------------------------------------------------------------------
__global__ void finalize_kernel(const int* __restrict__ idxp, float* __restrict__ out,
                                int out_size) {
    __shared__ float red[1024];
    int t = threadIdx.x;
    int idxv = *idxp;
    int K = (idxv == 0) ? 512 : 1024;
    float v = 0.f;
    if (t < K) {
        float pr = (float)g_hist[t] * (1.0f / (float)NPIX);
        v = pr * logf(pr + 1e-10f);
    }
    red[t] = v;
    __syncthreads();
    for (int off = 512; off > 0; off >>= 1) {
        if (t < off) red[t] += red[t + off];
        __syncthreads();
    }
    if (t == 0) {
        float mse = g_lossacc / (float)OUT_ELEMS;
        out[OUT_ELEMS]     = mse + 0.25f * mse;   // q_latent + 0.25*e_latent
        out[OUT_ELEMS + 1] = expf(-red[0]);       // perplexity
    }
    for (int i = OUT_ELEMS + 2 + t; i < out_size; i += 1024) out[i] = 0.f;
}

// ---------------------------------------------------------------------------
extern "C" void kernel_launch(void* const* d_in, const int* in_sizes, int n_in,
                              void* d_out, int out_size) {
    const float* x  = (const float*)d_in[0];
    const float* e0 = (const float*)d_in[1];
    const float* e1 = (const float*)d_in[2];
    const float* e2 = (const float*)d_in[3];
    const int*   ip = (const int*)d_in[4];
    float* out = (float*)d_out;

    cudaFuncSetAttribute(vq_hmma, cudaFuncAttributeMaxDynamicSharedMemorySize,
                         SMEM_TOTAL);

    prep_norms<<<256, 128>>>(e0, e1, e2, ip);
    prep_bsplit<<<KMAX, 64>>>(e0, e1, e2, ip);
    vq_hmma<<<NPIX / CTA_PIX, TPB, SMEM_TOTAL>>>(x, e0, e1, e2, ip, out);
    finalize_kernel<<<1, 1024>>>(ip, out, out_size);
}